// round 15
// baseline (speedup 1.0000x reference)
#include <cuda_runtime.h>
#include <cstdint>
#include <cstddef>

#define NBLK   16
#define RPB    128              // rows per block (4 per lane)
#define W      2048
#define H      2048
#define WSK    4096             // 4095 real skewed columns, padded to 4096
#define CH     16
#define NCHUNK (WSK / CH)       // 256
#define FC_IN  1024
#define FC_OUT 10
#define NFLAT  ((H * W) / FC_IN) // 4096

// ---- scratch (device globals: no runtime allocation allowed) ----
__device__ float g_unskew[(size_t)H * W];     // unskewed activations, row-major [r][c]
__device__ float g_bound[NBLK][WSK];          // last-row h value per column per block
__device__ int   g_progress[NBLK][32];        // one 128B L2 line per block

__device__ __forceinline__ int acq_load(const int* p) {
    int v;
    asm volatile("ld.acquire.gpu.global.s32 %0, [%1];" : "=r"(v) : "l"(p) : "memory");
    return v;
}
__device__ __forceinline__ void rel_store(int* p, int v) {
    asm volatile("st.release.gpu.global.s32 [%0], %1;" :: "l"(p), "r"(v) : "memory");
}
// L2-only load: immune to stale L1 lines for producer-written data
__device__ __forceinline__ float ldcg(const float* p) {
    float v;
    asm volatile("ld.global.cg.f32 %0, [%1];" : "=f"(v) : "l"(p));
    return v;
}
// Hardware tanh (MUFU.TANH): 1 op on the chain.
__device__ __forceinline__ float htanh(float z) {
    float r;
    asm("tanh.approx.f32 %0, %1;" : "=f"(r) : "f"(z));
    return r;
}

// 4 warps per block (each on its own SMSP):
//   warp 0: compute — lane l owns rows base+4l .. base+4l+3. All z's of a
//           column use only previous-column h's, so the 4 tanhs are parallel;
//           per-column rate = (4*24 + 46)/4 = 29.5 cy. Lane 31 publishes the
//           block's last row (g_bound + release flag) directly.
//   warp 1: image load/stage + act flush for rows 0-63.
//   warp 2: same for rows 64-127.
//   warp 3: boundary sync — polls upstream flag, fetches boundary chunk n+2.
// Tile layout: [CH][RPB], element (row r, col cc) at [cc][((r>>2)^(cc&7))*4 + (r&3)].
// Compute float4 accesses at ((lane^(cc&7))*4) and memory-warp scalar accesses
// are both bank-conflict-free under this swizzle.
// Recurrence: h_new[r] = tanh(k0*h_old[r-1] + k1*h_old[r] + pre), pre = w*img + cb.
__global__ void __launch_bounds__(128, 1) scan_kernel(
    const float* __restrict__ img, const float* __restrict__ w_in,
    const float* __restrict__ b_in, const float* __restrict__ w_state,
    const float* __restrict__ b_state)
{
    __shared__ __align__(16) float s_img[3][CH][RPB];  // pre-affine inputs, chunk n in buf n%3
    __shared__ __align__(16) float s_act[2][CH][RPB];  // h-space acts, chunk n in buf n&1
    __shared__ __align__(16) float s_bnd[3][CH];       // boundary h, chunk n in buf n%3

    const int b    = blockIdx.x;
    const int tid  = threadIdx.x;
    const int lane = tid & 31;
    const int wid  = tid >> 5;
    const int base = b * RPB;

    const float w  = w_in[0];
    const float k0 = w_state[0];
    const float k1 = w_state[1];
    const float cb = b_in[0] + b_state[0];

    if (wid == 0) {
        // ================= compute warp =================
        const float k0_up = (lane == 0) ? 0.0f : k0;   // lane0: ignore shfl_up
        const float k0_b  = (lane == 0) ? k0   : 0.0f; // lane0: use boundary value
        float h0 = 0.f, h1 = 0.f, h2 = 0.f, h3 = 0.f;  // rows base+4l .. +3
        float* brow = g_bound[b];
        float b16[CH];                    // lane 31: block-last-row values

        for (int n = 0; n < NCHUNK; n++) {
            __syncthreads();              // img/bnd chunk n ready; act[n&1] free
            const int ib = n % 3;
            const int ab = n & 1;
            float4 pc = *(const float4*)&s_img[ib][0][(lane ^ 0) * 4];
#pragma unroll
            for (int cc = 0; cc < CH; cc++) {
                float4 pn;
                if (cc + 1 < CH)          // prefetch next column (off-chain)
                    pn = *(const float4*)&s_img[ib][cc + 1][(lane ^ ((cc + 1) & 7)) * 4];
                float bnd = s_bnd[ib][cc];                      // LDS broadcast
                float up  = __shfl_up_sync(0xffffffffu, h3, 1); // row 4l-1 (old)
                float q0 = fmaf(k0_b, bnd, pc.x);               // off-chain fold
                float z0 = fmaf(k0_up, up, fmaf(k1, h0, q0));
                float z1 = fmaf(k0, h0, fmaf(k1, h1, pc.y));    // all old h's
                float z2 = fmaf(k0, h1, fmaf(k1, h2, pc.z));
                float z3 = fmaf(k0, h2, fmaf(k1, h3, pc.w));
                h0 = htanh(z0); h1 = htanh(z1); h2 = htanh(z2); h3 = htanh(z3);
                *(float4*)&s_act[ab][cc][(lane ^ (cc & 7)) * 4] =
                    make_float4(h0, h1, h2, h3);
                b16[cc] = h3;
                pc = pn;
            }
            // lane 31 (row base+127 = block's last row) publishes boundary now.
            if (lane == 31) {
                float4* dst = (float4*)(brow + n * CH);
                dst[0] = make_float4(b16[0],  b16[1],  b16[2],  b16[3]);
                dst[1] = make_float4(b16[4],  b16[5],  b16[6],  b16[7]);
                dst[2] = make_float4(b16[8],  b16[9],  b16[10], b16[11]);
                dst[3] = make_float4(b16[12], b16[13], b16[14], b16[15]);
                rel_store(&g_progress[b][0], (n + 1) * CH);     // release: orders STGs
            }
        }
        __syncthreads();                  // final: hand last act tile to mem warps
    } else if (wid <= 2) {
        // ================= image / activation warps (rows 0-63 / 64-127) =====
        const int roff = (wid - 1) * 64;  // local row offset for this warp
        const int fr = lane >> 3;         // 0..3 : row sub-index within group
        const int fc = lane & 7;          // 0..7 : column sub-index
        int Bidx[16], off[16], eidx[16];  // chunk m: global addr = Bidx + 16*m (+8)
#pragma unroll
        for (int it = 0; it < 16; it++) {
            int rl   = roff + it * 4 + fr;         // local row 0..127
            int gr   = base + rl;                  // global row
            off[it]  = fc - gr;                    // global col = a + off (+8)
            Bidx[it] = gr * (W - 1) + fc;          // unskew/img addr = Bidx + a (+8)
            eidx[it] = ((rl >> 2) ^ fc) * 4 + (rl & 3);  // swizzled element
        }

        // prologue: img chunks 0,1 -> smem (pre-affine); chunk 2 -> regs (raw)
        float rg[32];
#pragma unroll
        for (int it = 0; it < 16; it++) {
            int o = off[it];
            { int c = o;      s_img[0][fc][eidx[it]]   = ((unsigned)c < W) ? fmaf(w, img[Bidx[it]],      cb) : cb; }
            { int c = o + 8;  s_img[0][fc+8][eidx[it]] = ((unsigned)c < W) ? fmaf(w, img[Bidx[it] + 8],  cb) : cb; }
            { int c = o + 16; s_img[1][fc][eidx[it]]   = ((unsigned)c < W) ? fmaf(w, img[Bidx[it] + 16], cb) : cb; }
            { int c = o + 24; s_img[1][fc+8][eidx[it]] = ((unsigned)c < W) ? fmaf(w, img[Bidx[it] + 24], cb) : cb; }
            { int c = o + 32; rg[2*it]                 = ((unsigned)c < W) ? img[Bidx[it] + 32] : 0.f; }
            { int c = o + 40; rg[2*it+1]               = ((unsigned)c < W) ? img[Bidx[it] + 40] : 0.f; }
        }

        for (int n = 0; n < NCHUNK; n++) {
            __syncthreads();
            const int m2 = n + 2, m3 = n + 3;
            // publish staged img chunk n+2 into smem (apply affine here)
            if (m2 < NCHUNK) {
                const int bi = m2 % 3;
#pragma unroll
                for (int it = 0; it < 16; it++) {
                    s_img[bi][fc][eidx[it]]   = fmaf(w, rg[2*it],   cb);
                    s_img[bi][fc+8][eidx[it]] = fmaf(w, rg[2*it+1], cb);
                }
            }
            // issue img loads for chunk n+3 (one full window of latency slack)
            if (m3 < NCHUNK) {
                const int a = m3 * CH;
#pragma unroll
                for (int it = 0; it < 16; it++) {
                    int c0 = a + off[it];
                    rg[2*it]   = ((unsigned)c0 < W)     ? img[Bidx[it] + a]     : 0.f;
                    rg[2*it+1] = ((unsigned)(c0+8) < W) ? img[Bidx[it] + a + 8] : 0.f;
                }
            }
            // flush activation tile of chunk n-1 (coalesced)
            if (n >= 1) {
                const int fb = (n - 1) & 1;
                const int a  = (n - 1) * CH;
#pragma unroll
                for (int it = 0; it < 16; it++) {
                    int c0 = a + off[it];
                    float v0 = s_act[fb][fc][eidx[it]];
                    float v1 = s_act[fb][fc+8][eidx[it]];
                    if ((unsigned)c0 < W)     g_unskew[Bidx[it] + a]     = v0;
                    if ((unsigned)(c0+8) < W) g_unskew[Bidx[it] + a + 8] = v1;
                }
            }
        }
        __syncthreads();
        // epilogue: flush final activation chunk
        {
            const int fb = (NCHUNK - 1) & 1;
            const int a  = (NCHUNK - 1) * CH;
#pragma unroll
            for (int it = 0; it < 16; it++) {
                int c0 = a + off[it];
                float v0 = s_act[fb][fc][eidx[it]];
                float v1 = s_act[fb][fc+8][eidx[it]];
                if ((unsigned)c0 < W)     g_unskew[Bidx[it] + a]     = v0;
                if ((unsigned)(c0+8) < W) g_unskew[Bidx[it] + a + 8] = v1;
            }
        }
    } else {
        // ================= boundary-sync warp =================
        const float* ub     = (b > 0) ? g_bound[b - 1] : g_bound[0];
        const int*   upflag = (b > 0) ? &g_progress[b - 1][0] : &g_progress[0][0];
        int kn = 0;

        // prologue: chunks 0,1 (zeros above the image for block 0)
        if (lane < CH) { s_bnd[0][lane] = 0.f; s_bnd[1][lane] = 0.f; s_bnd[2][lane] = 0.f; }
        if (b > 0) {
            while (kn < CH - 1) kn = acq_load(upflag);
            if (lane > 0 && lane < CH) s_bnd[0][lane] = ldcg(ub + lane - 1);
            while (kn < 2 * CH - 1) kn = acq_load(upflag);
            if (lane < CH) s_bnd[1][lane] = ldcg(ub + CH - 1 + lane);
        }

        for (int n = 0; n < NCHUNK; n++) {
            __syncthreads();
            // fetch boundary chunk n+2 (distance-2: poll + L2 latency fully
            // overlapped with warps 0-2; consumed 2 barriers later)
            const int m = n + 2;
            if (b > 0 && m < NCHUNK) {
                const int need = (m + 1) * CH - 1;
                while (kn < need) kn = acq_load(upflag);
                if (lane < CH) s_bnd[m % 3][lane] = ldcg(ub + m * CH - 1 + lane);
            }
        }
        __syncthreads();
    }
}

// out[f][o] = dot(unskew_flat[f], fc_w[o]) + fc_b[o]; 10 warps, one per output
__global__ void fc_kernel(const float* __restrict__ fc_w, const float* __restrict__ fc_b,
                          float* __restrict__ out) {
    __shared__ float4 sact[FC_IN / 4];
    const int f = blockIdx.x;
    const float4* src = (const float4*)(g_unskew + (size_t)f * FC_IN);
    if (threadIdx.x < FC_IN / 4) sact[threadIdx.x] = src[threadIdx.x];
    __syncthreads();
    const int wid  = threadIdx.x >> 5;
    const int lane = threadIdx.x & 31;
    if (wid < FC_OUT) {
        const float4* wr = (const float4*)(fc_w + (size_t)wid * FC_IN);
        float acc = 0.0f;
#pragma unroll
        for (int i = 0; i < 8; i++) {
            float4 a  = sact[lane + i * 32];
            float4 wv = wr[lane + i * 32];
            acc = fmaf(a.x, wv.x, acc);
            acc = fmaf(a.y, wv.y, acc);
            acc = fmaf(a.z, wv.z, acc);
            acc = fmaf(a.w, wv.w, acc);
        }
#pragma unroll
        for (int s = 16; s > 0; s >>= 1) acc += __shfl_down_sync(0xffffffffu, acc, s);
        if (lane == 0) out[f * FC_OUT + wid] = acc + fc_b[wid];
    }
}

// Clears progress flags AFTER each invocation so the next replay starts clean.
// (Globals are zero-initialized, so the very first call is also clean.)
__global__ void reset_kernel() {
    ((int*)g_progress)[threadIdx.x] = 0;
}

extern "C" void kernel_launch(void* const* d_in, const int* in_sizes, int n_in,
                              void* d_out, int out_size) {
    const float* x       = (const float*)d_in[0];
    const float* w_in    = (const float*)d_in[1];
    const float* b_in    = (const float*)d_in[2];
    const float* w_state = (const float*)d_in[3];
    const float* b_state = (const float*)d_in[4];
    const float* fc_w    = (const float*)d_in[5];
    const float* fc_b    = (const float*)d_in[6];
    (void)in_sizes; (void)n_in; (void)out_size;

    scan_kernel<<<NBLK, 128>>>(x, w_in, b_in, w_state, b_state);
    fc_kernel<<<NFLAT, 320>>>(fc_w, fc_b, (float*)d_out);
    reset_kernel<<<1, NBLK * 32>>>();   // flags clean for the next graph replay
}